// round 10
// baseline (speedup 1.0000x reference)
#include <cuda_runtime.h>

// img:  (1, 64, 64, 1024) float32
// rois: (1, 1024, 4) int32  -> x, y, w, h
// out:  (1, 1024, 7, 7, 1024) float32
//
// One CTA per (roi, py); 256 threads, one float4 channel lane each.
// Fully unrolled px loop, 28 independent __ldg gathers. Coordinate math is
// recomputed per px (block-uniform, cheap) instead of precomputed arrays to
// cut ~21 registers; __launch_bounds__(256,5) -> 48 regs, 5 CTAs/SM for
// better L1 latency hiding. Stores use __stcs (streaming) so the 205MB write
// stream doesn't evict the 16.7MB img working set from L2.

#define POOL 7
#define HW 64
#define CV 256   // float4 lanes per pixel

__global__ __launch_bounds__(256, 5) void roi_pool_kernel(
    const float* __restrict__ img_,
    const int* __restrict__ rois,
    float* __restrict__ out_)
{
    const float4* __restrict__ img = reinterpret_cast<const float4*>(img_);
    float4* __restrict__ out = reinterpret_cast<float4*>(out_);

    const int py  = blockIdx.x;   // 0..6
    const int roi = blockIdx.y;   // 0..1023

    const int4 r = reinterpret_cast<const int4*>(rois)[roi];
    const int rx = r.x, ry = r.y, rw = r.z, rh = r.w;

    // ---- y axis (once per block) ----
    const float sy   = (float)rh / (float)POOL;
    const float srcy = ((float)py + 0.5f) * sy - 0.5f;
    const float fy   = floorf(srcy);
    const float ty   = srcy - fy;
    const int ylo = min(max((int)fy,     0), rh - 1);
    const int yhi = min(max((int)fy + 1, 0), rh - 1);

    const float4* __restrict__ rowT = img + (size_t)((ry + ylo) * HW) * CV;
    const float4* __restrict__ rowB = img + (size_t)((ry + yhi) * HW) * CV;

    const int c = threadIdx.x;
    float4* __restrict__ o = out + ((size_t)roi * (POOL * POOL) + (size_t)py * POOL) * CV + c;

    const float sx   = (float)rw / (float)POOL;
    const float wty  = ty;
    const float wmty = 1.0f - ty;

    #pragma unroll
    for (int px = 0; px < POOL; px++) {
        // per-px coords (block-uniform, recomputed to save registers)
        const float srcx = ((float)px + 0.5f) * sx - 0.5f;
        const float fx   = floorf(srcx);
        const float wtx  = srcx - fx;
        const float wmtx = 1.0f - wtx;
        const int xlo = min(max((int)fx,     0), rw - 1);
        const int xhi = min(max((int)fx + 1, 0), rw - 1);
        const int xa = rx + xlo;
        const int xb = rx + xhi;

        const float4 ta = __ldg(rowT + (size_t)xa * CV + c);
        const float4 tb = __ldg(rowT + (size_t)xb * CV + c);
        const float4 ba = __ldg(rowB + (size_t)xa * CV + c);
        const float4 bb = __ldg(rowB + (size_t)xb * CV + c);

        float4 res;
        res.x = (ta.x * wmtx + tb.x * wtx) * wmty + (ba.x * wmtx + bb.x * wtx) * wty;
        res.y = (ta.y * wmtx + tb.y * wtx) * wmty + (ba.y * wmtx + bb.y * wtx) * wty;
        res.z = (ta.z * wmtx + tb.z * wtx) * wmty + (ba.z * wmtx + bb.z * wtx) * wty;
        res.w = (ta.w * wmtx + tb.w * wtx) * wmty + (ba.w * wmtx + bb.w * wtx) * wty;

        __stcs(o + px * CV, res);
    }
}

extern "C" void kernel_launch(void* const* d_in, const int* in_sizes, int n_in,
                              void* d_out, int out_size)
{
    const float* img  = (const float*)d_in[0];
    const int*   rois = (const int*)d_in[1];
    float*       out  = (float*)d_out;

    dim3 grid(POOL, 1024);
    roi_pool_kernel<<<grid, 256>>>(img, rois, out);
}